// round 16
// baseline (speedup 1.0000x reference)
#include <cuda_runtime.h>
#include <cuda_bf16.h>
#include <math.h>
#include <stdint.h>
#include <stddef.h>

#define Bn 256
#define Ln 512
#define Cn 32

// ---------------- scratch offsets (floats) ----------------
#define OFF_XNP   0u           // xn pairs      4,194,304 fl (hi|lo bf16 planes)
#define OFF_MEAN  4194304u
#define OFF_STD   4202496u
#define OFF_KC    4210688u     // circulant pairs [4][hi|lo]   1,048,576 fl
#define OFF_XIP   5259264u     // XI pairs [4][hi|lo]          16,777,216 fl
#define OFF_E1P   22036480u    // 8,388,608 fl
#define OFF_E2P   30425088u    // 4,194,304 fl
#define OFF_XPP   34619392u    // 4,194,304 fl
#define OFF_RP    38813696u    // R pairs [4][12][hi|lo]       12,582,912 fl
#define OFF_SP    51396608u    // S pairs [4][9][hi|lo]        9,437,184 fl
#define OFF_PRF   60833792u    // PR fp32                      2,097,152 fl
#define OFF_PRP   62930944u    // PR pairs [4][hi|lo]          2,097,152 fl
#define OFF_DHP   65028096u    // DH pairs [4][hi|lo]          4,194,304 fl
#define OFF_EW1P  69222400u    // 8,388,608 fl
#define OFF_EW2P  77611008u    // 2,097,152 fl
#define OFF_WXHP  79708160u    // 1,048,576 fl
#define OFF_DW1P  80756736u    // 2,097,152 fl
#define OFF_DW2P  82853888u    // 8,388,608 fl
#define OFF_KF    91242496u    // fp32 taps [4][512]
#define SCR_TOTAL 91244544u

__device__ __align__(1024) float g_scratch[SCR_TOTAL];

typedef __nv_bfloat16 bf16;

__device__ __forceinline__ uint32_t smem_u32(const void* p) {
    uint32_t a;
    asm("{ .reg .u64 t; cvta.to.shared.u64 t, %1; cvt.u32.u64 %0, t; }" : "=r"(a) : "l"(p));
    return a;
}

#define CP16(dst, src) \
    asm volatile("cp.async.cg.shared.global [%0], [%1], 16;" :: "r"(dst), "l"(src))
#define CP_COMMIT() asm volatile("cp.async.commit_group;" ::: "memory")

#define LDSM4(r, a) \
    asm volatile("ldmatrix.sync.aligned.m8n8.x4.shared.b16 {%0,%1,%2,%3}, [%4];" \
        : "=r"((r)[0]), "=r"((r)[1]), "=r"((r)[2]), "=r"((r)[3]) : "r"(a))
#define LDSM2(r, a) \
    asm volatile("ldmatrix.sync.aligned.m8n8.x2.shared.b16 {%0,%1}, [%2];" \
        : "=r"((r)[0]), "=r"((r)[1]) : "r"(a))
#define MMA16816(d, a, b) \
    asm volatile("mma.sync.aligned.m16n8k16.row.col.f32.bf16.bf16.f32 " \
        "{%0,%1,%2,%3}, {%4,%5,%6,%7}, {%8,%9}, {%0,%1,%2,%3};" \
        : "+f"((d)[0]), "+f"((d)[1]), "+f"((d)[2]), "+f"((d)[3]) \
        : "r"((a)[0]), "r"((a)[1]), "r"((a)[2]), "r"((a)[3]), "r"((b)[0]), "r"((b)[1]))

__device__ __forceinline__ void pack2(uint32_t& h, uint32_t& l, float va, float vb) {
    asm("cvt.rn.bf16x2.f32 %0, %1, %2;" : "=r"(h) : "f"(vb), "f"(va));
    float fa = __uint_as_float(h << 16);
    float fb = __uint_as_float(h & 0xFFFF0000u);
    asm("cvt.rn.bf16x2.f32 %0, %1, %2;" : "=r"(l) : "f"(vb - fb), "f"(va - fa));
}

// ===========================================================================
// HMMA NT GEMM on preconverted bf16 hi/lo pairs. C[m,n] = sum A[m,k]*B[n,k].
// 3-term split (AhBh + AhBl + AlBh), fp32 acc. CTA 128x128, 8 warps 64x32.
// cp.async 2-stage pipeline. LA/LB/LC = element offset of the lo plane.
// AG: 0 row-major A[row*K+k]; 1 dec2 DH gather [(k>>10)*2097152 + row*1024+...]
// GB: 0 row-major; 1 RNN R-pair gather; 3 dec2 dw2 gather
// EPI: 0 pair-store (+bias/relu); 1 conv scatter to XI pairs; 2 dec2-final
//      fp32 out; 3 plain fp32 store
// ===========================================================================
struct TCArgs {
    const bf16* A[32];
    const bf16* B[32];
    const float* bias[32];
    void*       C[32];
    const float* mean;
    const float* stdv;
};

#define PLANE 10240u   // 128 rows * 40 bf16 * 2B
#define STAGE 40960u   // Ah Al Bh Bl
#define DYNSM 81920u

template<int AG, int GB, int EPI, bool BIAS, bool RELU>
__global__ __launch_bounds__(256, 2) void tc_gemm(
    const TCArgs ta, int M, int N, int K, int LA, int LB, int LC)
{
    extern __shared__ char smem[];
    const uint32_t sbase = smem_u32(smem);
    const int tid = threadIdx.x, wid = tid >> 5, lane = tid & 31;
    const int z = blockIdx.z;
    const int m0 = blockIdx.y * 128, n0 = blockIdx.x * 128;
    const bf16* __restrict__ Ab = ta.A[z];
    const bf16* __restrict__ Bb = ta.B[z];
    const int S = K >> 5;
    const int wm = (wid & 1) * 64;
    const int wn = (wid >> 1) * 32;

    float acc[4][4][4];
#pragma unroll
    for (int i = 0; i < 4; i++)
#pragma unroll
        for (int j = 0; j < 4; j++)
#pragma unroll
            for (int q = 0; q < 4; q++) acc[i][j][q] = 0.f;

    auto issue = [&](int s) {
        const uint32_t sb = sbase + (uint32_t)(s & 1) * STAGE;
        const int k0 = s * 32;
#pragma unroll
        for (int rep = 0; rep < 2; rep++) {
            const int chunk = rep * 256 + tid;
            const int row = chunk >> 2, c = chunk & 3;
            const int kc = k0 + c * 8;
            const uint32_t d = sb + (uint32_t)(row * 80 + c * 16);
            const bf16* pa;
            if (AG == 0) pa = Ab + (size_t)(m0 + row) * K + kc;
            else         pa = Ab + ((size_t)(kc >> 10) << 21) + (size_t)(m0 + row) * 1024 + (kc & 1023);
            CP16(d, pa);
            CP16(d + PLANE, pa + LA);
            const int n = n0 + row;
            const bf16* pb;
            if (GB == 0)      pb = Bb + (size_t)n * K + kc;
            else if (GB == 1) pb = Bb + (size_t)(8 + (n >> 9) - (kc >> 9)) * 524288
                                   + ((size_t)(n & 511) << 9) + (kc & 511);
            else              pb = Bb + (size_t)(kc >> 10) * 2097152u + (size_t)n * 1024 + (kc & 1023);
            CP16(d + 2 * PLANE, pb);
            CP16(d + 3 * PLANE, pb + LB);
        }
        CP_COMMIT();
    };

    issue(0);
    if (S > 1) issue(1);

    for (int s = 0; s < S; s++) {
        if (s + 1 < S) asm volatile("cp.async.wait_group 1;" ::: "memory");
        else           asm volatile("cp.async.wait_group 0;" ::: "memory");
        __syncthreads();
        const uint32_t sA = sbase + (uint32_t)(s & 1) * STAGE;
        const uint32_t sB = sA + 2 * PLANE;
#pragma unroll
        for (int kk = 0; kk < 32; kk += 16) {
            uint32_t ah[4][4], al[4][4];
#pragma unroll
            for (int i = 0; i < 4; i++) {
                uint32_t a = sA + (uint32_t)((wm + 16 * i + (lane & 15)) * 80
                                             + (kk + ((lane >> 4) << 3)) * 2);
                LDSM4(ah[i], a);
                LDSM4(al[i], a + PLANE);
            }
#pragma unroll
            for (int j = 0; j < 4; j++) {
                uint32_t bh[2], bl[2];
                uint32_t a = sB + (uint32_t)((wn + 8 * j + (lane & 7)) * 80
                                             + (kk + (((lane >> 3) & 1) << 3)) * 2);
                LDSM2(bh, a);
                LDSM2(bl, a + PLANE);
#pragma unroll
                for (int i = 0; i < 4; i++) {
                    MMA16816(acc[i][j], ah[i], bh);
                    MMA16816(acc[i][j], ah[i], bl);
                    MMA16816(acc[i][j], al[i], bh);
                }
            }
        }
        __syncthreads();
        if (s + 2 < S) issue(s + 2);
    }

    if (EPI == 0) {
        bf16* Cb = (bf16*)ta.C[z];
        const float* bb = BIAS ? ta.bias[z] : (const float*)0;
#pragma unroll
        for (int i = 0; i < 4; i++) {
            const int m = m0 + wm + 16 * i + (lane >> 2);
#pragma unroll
            for (int j = 0; j < 4; j++) {
                const int n = n0 + wn + 8 * j + (lane & 3) * 2;
                float v0 = acc[i][j][0], v1 = acc[i][j][1];
                float v2 = acc[i][j][2], v3 = acc[i][j][3];
                if (BIAS) {
                    float2 b2 = *(const float2*)(bb + n);
                    v0 += b2.x; v1 += b2.y; v2 += b2.x; v3 += b2.y;
                }
                if (RELU) {
                    v0 = fmaxf(v0, 0.f); v1 = fmaxf(v1, 0.f);
                    v2 = fmaxf(v2, 0.f); v3 = fmaxf(v3, 0.f);
                }
                uint32_t h, l;
                size_t o = (size_t)m * N + n;
                pack2(h, l, v0, v1);
                *(uint32_t*)(Cb + o) = h;
                *(uint32_t*)(Cb + o + LC) = l;
                o = (size_t)(m + 8) * N + n;
                pack2(h, l, v2, v3);
                *(uint32_t*)(Cb + o) = h;
                *(uint32_t*)(Cb + o + LC) = l;
            }
        }
    } else if (EPI == 1) {
        __syncthreads();
        float* T = (float*)smem;
#pragma unroll
        for (int i = 0; i < 4; i++) {
            const int mi = wm + 16 * i + (lane >> 2);
#pragma unroll
            for (int j = 0; j < 4; j++) {
                const int nj = wn + 8 * j + (lane & 3) * 2;
                T[mi * 129 + nj]           = acc[i][j][0];
                T[mi * 129 + nj + 1]       = acc[i][j][1];
                T[(mi + 8) * 129 + nj]     = acc[i][j][2];
                T[(mi + 8) * 129 + nj + 1] = acc[i][j][3];
            }
        }
        __syncthreads();
        const int b0 = blockIdx.y * 4, f0 = blockIdx.x * 2;
        const int rr = tid >> 5;
        const int bloc = rr >> 1, floc = rr & 1;
        bf16* xrow = (bf16*)ta.C[z] + (size_t)((b0 + bloc) * 8 + f0 + floc) * 2048;
#pragma unroll
        for (int jj = 0; jj < 16; jj++) {
            const int j = (jj * 32 + lane) * 4;
            const int p = j >> 5, c = j & 31;
            float v0 = T[(bloc * 32 + c)     * 129 + floc * 64 + p];
            float v1 = T[(bloc * 32 + c + 1) * 129 + floc * 64 + p];
            float v2 = T[(bloc * 32 + c + 2) * 129 + floc * 64 + p];
            float v3 = T[(bloc * 32 + c + 3) * 129 + floc * 64 + p];
            uint32_t h0, l0, h1, l1;
            pack2(h0, l0, v0, v1);
            pack2(h1, l1, v2, v3);
            *(uint2*)(xrow + j) = make_uint2(h0, h1);
            *(uint2*)(xrow + j + LC) = make_uint2(l0, l1);
        }
    } else if (EPI == 2) {
        const float* bb = ta.bias[0];
        float* out = (float*)ta.C[0];
#pragma unroll
        for (int i = 0; i < 4; i++) {
            const int m = m0 + wm + 16 * i + (lane >> 2);
#pragma unroll
            for (int j = 0; j < 4; j++) {
                const int n = n0 + wn + 8 * j + (lane & 3) * 2;
                float b0s = bb[n]     + bb[2048 + n]     + bb[4096 + n]     + bb[6144 + n];
                float b1s = bb[n + 1] + bb[2048 + n + 1] + bb[4096 + n + 1] + bb[6144 + n + 1];
                {
                    const int b = m >> 2, c = n & 31;
                    const float sd  = ta.stdv[b * 32 + c],            mu  = ta.mean[b * 32 + c];
                    const float sd1 = ta.stdv[b * 32 + ((n + 1) & 31)], mu1 = ta.mean[b * 32 + ((n + 1) & 31)];
                    float2 v = make_float2(fmaf(acc[i][j][0] + b0s, sd, mu),
                                           fmaf(acc[i][j][1] + b1s, sd1, mu1));
                    *(float2*)(out + (size_t)b * 8192 + (m & 3) * 2048 + n) = v;
                }
                {
                    const int m8 = m + 8;
                    const int b = m8 >> 2, c = n & 31;
                    const float sd  = ta.stdv[b * 32 + c],            mu  = ta.mean[b * 32 + c];
                    const float sd1 = ta.stdv[b * 32 + ((n + 1) & 31)], mu1 = ta.mean[b * 32 + ((n + 1) & 31)];
                    float2 v = make_float2(fmaf(acc[i][j][2] + b0s, sd, mu),
                                           fmaf(acc[i][j][3] + b1s, sd1, mu1));
                    *(float2*)(out + (size_t)b * 8192 + (m8 & 3) * 2048 + n) = v;
                }
            }
        }
    } else {
        float* C = (float*)ta.C[z];
#pragma unroll
        for (int i = 0; i < 4; i++) {
            const int m = m0 + wm + 16 * i + (lane >> 2);
#pragma unroll
            for (int j = 0; j < 4; j++) {
                const int n = n0 + wn + 8 * j + (lane & 3) * 2;
                *(float2*)(C + (size_t)m * N + n) = make_float2(acc[i][j][0], acc[i][j][1]);
                *(float2*)(C + (size_t)(m + 8) * N + n) = make_float2(acc[i][j][2], acc[i][j][3]);
            }
        }
    }
}

// ---------------- stats: mean/std + xn pairs in [bc][l] layout -------------
__global__ __launch_bounds__(256) void stats_kernel(
    const float* __restrict__ x, bf16* __restrict__ xnp,
    float* __restrict__ meanA, float* __restrict__ stdA)
{
    __shared__ float red[2][8][32];
    __shared__ float mus[32], invs[32];
    __shared__ bf16 th[256][34], tl[256][34];
    const int b = blockIdx.x, tid = threadIdx.x;
    const int w = tid >> 5, lanec = tid & 31;
    const float* xb = x + (size_t)b * 16384;

    float s = 0.f, sq = 0.f;
    for (int k = 0; k < 64; k++) {
        float v = xb[k * 256 + tid];
        s += v; sq = fmaf(v, v, sq);
    }
    red[0][w][lanec] = s; red[1][w][lanec] = sq;
    __syncthreads();
    if (tid < 32) {
        float S8 = 0.f, Q8 = 0.f;
        for (int ww = 0; ww < 8; ww++) { S8 += red[0][ww][tid]; Q8 += red[1][ww][tid]; }
        float mu = S8 * (1.f / 512.f);
        float sd = sqrtf(Q8 * (1.f / 512.f) - mu * mu + 1e-5f);
        meanA[b * 32 + tid] = mu; stdA[b * 32 + tid] = sd;
        mus[tid] = mu; invs[tid] = 1.f / sd;
    }
    __syncthreads();

    for (int chunk = 0; chunk < 2; chunk++) {
        for (int k = 0; k < 32; k++) {
            int idx = chunk * 8192 + k * 256 + tid;
            int lr = k * 8 + (tid >> 5);
            float v = (xb[idx] - mus[lanec]) * invs[lanec];
            bf16 hv = __float2bfloat16(v);
            bf16 lv = __float2bfloat16(v - __bfloat162float(hv));
            th[lr][lanec] = hv; tl[lr][lanec] = lv;
        }
        __syncthreads();
        const int c = tid >> 3, seg = tid & 7;
        bf16* dh = xnp + ((size_t)(b * 32 + c)) * 512 + chunk * 256 + seg * 32;
        uint32_t u[16];
#pragma unroll
        for (int g = 0; g < 16; g++) {
            uint16_t a0 = *(uint16_t*)&th[seg * 32 + 2 * g][c];
            uint16_t a1 = *(uint16_t*)&th[seg * 32 + 2 * g + 1][c];
            u[g] = (uint32_t)a0 | ((uint32_t)a1 << 16);
        }
#pragma unroll
        for (int q = 0; q < 4; q++)
            *(uint4*)(dh + q * 8) = make_uint4(u[q*4], u[q*4+1], u[q*4+2], u[q*4+3]);
#pragma unroll
        for (int g = 0; g < 16; g++) {
            uint16_t a0 = *(uint16_t*)&tl[seg * 32 + 2 * g][c];
            uint16_t a1 = *(uint16_t*)&tl[seg * 32 + 2 * g + 1][c];
            u[g] = (uint32_t)a0 | ((uint32_t)a1 << 16);
        }
        bf16* dl = dh + 4194304;
#pragma unroll
        for (int q = 0; q < 4; q++)
            *(uint4*)(dl + q * 8) = make_uint4(u[q*4], u[q*4+1], u[q*4+2], u[q*4+3]);
        __syncthreads();
    }
}

__global__ __launch_bounds__(512) void filter_kernel(
    const float* __restrict__ mw, float* __restrict__ Kf)
{
    int nb = blockIdx.x, t = threadIdx.x;
    const float* m = mw + nb * 257;
    float s0 = 1.f / (1.f + expf(-m[0]));
    float s256 = 1.f / (1.f + expf(-m[256]));
    float acc = s0 + ((t & 1) ? -s256 : s256);
    const float step = 6.283185307179586f / 512.f;
    for (int f = 1; f < 256; f++) {
        float sf = 1.f / (1.f + expf(-m[f]));
        acc = fmaf(2.f * sf, cosf(step * (float)((f * t) & 511)), acc);
    }
    Kf[nb * 512 + t] = acc * (1.f / 512.f);
}

// circulant pair matrix: Kc[nb][n][k] = tap[(n-k)&511]
__global__ __launch_bounds__(512) void build_kc(
    const float* __restrict__ Kf, bf16* __restrict__ kcp)
{
    __shared__ float t[512];
    const int nb = blockIdx.y, n = blockIdx.x, k = threadIdx.x;
    t[k] = Kf[nb * 512 + k];
    __syncthreads();
    float v = t[(n - k) & 511];
    bf16 hv = __float2bfloat16(v);
    bf16 lv = __float2bfloat16(v - __bfloat162float(hv));
    size_t o = (size_t)nb * 524288 + (size_t)n * 512 + k;
    kcp[o] = hv; kcp[o + 262144] = lv;
}

// whh -> R1 pairs + S1 (=whh^T) pairs
__global__ __launch_bounds__(256) void prep_R(
    const float* __restrict__ whh, bf16* __restrict__ rp, bf16* __restrict__ sp)
{
    __shared__ float t[32][33];
    const int nb = blockIdx.z;
    const float* in = whh + (size_t)nb * 262144;
    bf16* rd = rp + ((size_t)nb * 12 + 1) * 524288;
    bf16* sd = sp + ((size_t)nb * 9 + 1) * 524288;
    const int x0 = blockIdx.x * 32, y0 = blockIdx.y * 32;
    const int tx = threadIdx.x & 31, ty = threadIdx.x >> 5;
#pragma unroll
    for (int j = 0; j < 32; j += 8) {
        float v = in[(y0 + ty + j) * 512 + x0 + tx];
        bf16 hv = __float2bfloat16(v);
        bf16 lv = __float2bfloat16(v - __bfloat162float(hv));
        size_t o = (size_t)(y0 + ty + j) * 512 + x0 + tx;
        rd[o] = hv; rd[o + 262144] = lv;
        t[ty + j][tx] = v;
    }
    __syncthreads();
#pragma unroll
    for (int j = 0; j < 32; j += 8) {
        float v = t[tx][ty + j];
        bf16 hv = __float2bfloat16(v);
        bf16 lv = __float2bfloat16(v - __bfloat162float(hv));
        size_t o = (size_t)(x0 + ty + j) * 512 + y0 + tx;
        sd[o] = hv; sd[o + 262144] = lv;
    }
}

// generic fp32 -> bf16 hi/lo pair conversion (lo plane at out+E)
__global__ __launch_bounds__(256) void cvt_pairs(
    const float* __restrict__ in, bf16* __restrict__ out, int E)
{
    int i4 = (blockIdx.x * 256 + threadIdx.x) * 4;
    if (i4 >= E) return;
    float4 v = *(const float4*)(in + i4);
    uint32_t h0, l0, h1, l1;
    pack2(h0, l0, v.x, v.y);
    pack2(h1, l1, v.z, v.w);
    *(uint2*)(out + i4) = make_uint2(h0, h1);
    *(uint2*)(out + E + i4) = make_uint2(l0, l1);
}

// LayerNorm over 512: reads PR fp32, writes PR pairs
__global__ __launch_bounds__(256) void ln_kernel(
    const float* __restrict__ Pr, const float* __restrict__ g,
    const float* __restrict__ bta, bf16* __restrict__ prp)
{
    const int warp = threadIdx.x >> 5, lane = threadIdx.x & 31;
    const int row = blockIdx.x * 8 + warp;
    const int nb = row >> 10, r = row & 1023;
    const float* p = Pr + (size_t)row * 512;
    float v[16], s = 0.f, sq = 0.f;
#pragma unroll
    for (int i = 0; i < 16; i++) { v[i] = p[lane + 32 * i]; s += v[i]; sq = fmaf(v[i], v[i], sq); }
#pragma unroll
    for (int off = 16; off > 0; off >>= 1) {
        s += __shfl_xor_sync(0xFFFFFFFFu, s, off);
        sq += __shfl_xor_sync(0xFFFFFFFFu, sq, off);
    }
    float mu = s * (1.f / 512.f);
    float rs = rsqrtf(sq * (1.f / 512.f) - mu * mu + 1e-5f);
    const float* gg = g + nb * 512;
    const float* bb = bta + nb * 512;
    bf16* oh = prp + (size_t)nb * 1048576 + (size_t)r * 512;
#pragma unroll
    for (int i = 0; i < 16; i++) {
        int d = lane + 32 * i;
        float y = fmaf((v[i] - mu) * rs, gg[d], bb[d]);
        bf16 hv = __float2bfloat16(y);
        oh[d] = hv;
        oh[d + 524288] = __float2bfloat16(y - __bfloat162float(hv));
    }
}

// ---------------- launcher ----------------
extern "C" void kernel_launch(void* const* d_in, const int* in_sizes, int n_in,
                              void* d_out, int out_size)
{
    (void)in_sizes; (void)n_in; (void)out_size;
    const float* x_enc = (const float*)d_in[0];
    const float* maskw = (const float*)d_in[4];
    const float* ew1 = (const float*)d_in[5];
    const float* eb1 = (const float*)d_in[6];
    const float* ew2 = (const float*)d_in[7];
    const float* eb2 = (const float*)d_in[8];
    const float* wxh = (const float*)d_in[9];
    const float* whh = (const float*)d_in[10];
    const float* lng = (const float*)d_in[11];
    const float* lnb = (const float*)d_in[12];
    const float* dw1 = (const float*)d_in[13];
    const float* db1 = (const float*)d_in[14];
    const float* dw2 = (const float*)d_in[15];
    const float* db2 = (const float*)d_in[16];
    float* out = (float*)d_out;

    float* S = nullptr;
    cudaGetSymbolAddress((void**)&S, g_scratch);
    bf16* xnp  = (bf16*)(S + OFF_XNP);
    float* mnA = S + OFF_MEAN;  float* sdA = S + OFF_STD;  float* Kf = S + OFF_KF;
    bf16* kcp  = (bf16*)(S + OFF_KC);
    bf16* xip  = (bf16*)(S + OFF_XIP);
    bf16* e1p  = (bf16*)(S + OFF_E1P);
    bf16* e2p  = (bf16*)(S + OFF_E2P);
    bf16* xpp  = (bf16*)(S + OFF_XPP);
    bf16* rp   = (bf16*)(S + OFF_RP);
    bf16* sp   = (bf16*)(S + OFF_SP);
    float* prf = S + OFF_PRF;
    bf16* prp  = (bf16*)(S + OFF_PRP);
    bf16* dhp  = (bf16*)(S + OFF_DHP);
    bf16* ew1p = (bf16*)(S + OFF_EW1P);
    bf16* ew2p = (bf16*)(S + OFF_EW2P);
    bf16* wxhp = (bf16*)(S + OFF_WXHP);
    bf16* dw1p = (bf16*)(S + OFF_DW1P);
    bf16* dw2p = (bf16*)(S + OFF_DW2P);

    cudaFuncSetAttribute(tc_gemm<0,0,1,false,false>, cudaFuncAttributeMaxDynamicSharedMemorySize, DYNSM);
    cudaFuncSetAttribute(tc_gemm<0,0,0,false,false>, cudaFuncAttributeMaxDynamicSharedMemorySize, DYNSM);
    cudaFuncSetAttribute(tc_gemm<0,0,0,true,true>,   cudaFuncAttributeMaxDynamicSharedMemorySize, DYNSM);
    cudaFuncSetAttribute(tc_gemm<0,0,0,true,false>,  cudaFuncAttributeMaxDynamicSharedMemorySize, DYNSM);
    cudaFuncSetAttribute(tc_gemm<0,1,3,false,false>, cudaFuncAttributeMaxDynamicSharedMemorySize, DYNSM);
    cudaFuncSetAttribute(tc_gemm<1,3,2,false,false>, cudaFuncAttributeMaxDynamicSharedMemorySize, DYNSM);

    auto Rp = [&](int nb, int t) -> bf16* { return rp + ((size_t)nb * 12 + t) * 524288; };
    auto Sp = [&](int nb, int t) -> bf16* { return sp + ((size_t)nb * 9 + t) * 524288; };

    TCArgs ga;
    ga.mean = mnA; ga.stdv = sdA;

    stats_kernel<<<256, 256>>>(x_enc, xnp, mnA, sdA);            // 0
    filter_kernel<<<4, 512>>>(maskw, Kf);                        // 1
    build_kc<<<dim3(512, 4), 512>>>(Kf, kcp);                    // 2
    prep_R<<<dim3(16, 16, 4), 256>>>(whh, rp, sp);               // 3
    cvt_pairs<<<8192, 256>>>(ew1, ew1p, 8388608);                // 4

    // conv GEMM: XI pairs = xn-pairs @ circulant-pairs^T (EPI=1 scatter)  -- launch 5
    for (int nb = 0; nb < 4; nb++) {
        ga.A[nb] = xnp;
        ga.B[nb] = kcp + (size_t)nb * 524288;
        ga.C[nb] = xip + (size_t)nb * 8388608;
    }
    tc_gemm<0,0,1,false,false><<<dim3(4,64,4), 256, DYNSM>>>(ga, 8192, 512, 512,
                                                             4194304, 262144, 4194304);

    cvt_pairs<<<2048, 256>>>(ew2, ew2p, 2097152);
    cvt_pairs<<<1024, 256>>>(wxh, wxhp, 1048576);
    cvt_pairs<<<2048, 256>>>(dw1, dw1p, 2097152);
    cvt_pairs<<<8192, 256>>>(dw2, dw2p, 8388608);

    // power round 1
    for (int nb = 0; nb < 4; nb++) {
        ga.A[nb*2+0] = Rp(nb,1); ga.B[nb*2+0] = Sp(nb,1); ga.C[nb*2+0] = Rp(nb,2);
        ga.A[nb*2+1] = Sp(nb,1); ga.B[nb*2+1] = Rp(nb,1); ga.C[nb*2+1] = Sp(nb,2);
    }
    tc_gemm<0,0,0,false,false><<<dim3(4,4,8), 256, DYNSM>>>(ga, 512, 512, 512,
                                                            262144, 262144, 262144);
    // power round 2
    for (int nb = 0; nb < 4; nb++) {
        int z = nb * 4;
        ga.A[z+0] = Rp(nb,2); ga.B[z+0] = Sp(nb,1); ga.C[z+0] = Rp(nb,3);
        ga.A[z+1] = Rp(nb,2); ga.B[z+1] = Sp(nb,2); ga.C[z+1] = Rp(nb,4);
        ga.A[z+2] = Sp(nb,1); ga.B[z+2] = Rp(nb,2); ga.C[z+2] = Sp(nb,3);
        ga.A[z+3] = Sp(nb,2); ga.B[z+3] = Rp(nb,2); ga.C[z+3] = Sp(nb,4);
    }
    tc_gemm<0,0,0,false,false><<<dim3(4,4,16), 256, DYNSM>>>(ga, 512, 512, 512,
                                                             262144, 262144, 262144);
    // power round 3
    for (int nb = 0; nb < 4; nb++)
        for (int j = 1; j <= 4; j++) {
            int z = nb * 8 + (j - 1);
            ga.A[z] = Rp(nb,4); ga.B[z] = Sp(nb,j); ga.C[z] = Rp(nb,4+j);
            int z2 = nb * 8 + 4 + (j - 1);
            ga.A[z2] = Sp(nb,j); ga.B[z2] = Rp(nb,4); ga.C[z2] = Sp(nb,4+j);
        }
    tc_gemm<0,0,0,false,false><<<dim3(4,4,32), 256, DYNSM>>>(ga, 512, 512, 512,
                                                             262144, 262144, 262144);
    // power round 4
    for (int nb = 0; nb < 4; nb++)
        for (int j = 1; j <= 3; j++) {
            int z = nb * 3 + (j - 1);
            ga.A[z] = Rp(nb,8); ga.B[z] = Sp(nb,j); ga.C[z] = Rp(nb,8+j);
        }
    tc_gemm<0,0,0,false,false><<<dim3(4,4,12), 256, DYNSM>>>(ga, 512, 512, 512,
                                                             262144, 262144, 262144);

    // enc1
    for (int nb = 0; nb < 4; nb++) {
        ga.A[nb] = xip + (size_t)nb * 8388608;
        ga.B[nb] = ew1p + (size_t)nb * 2097152;
        ga.bias[nb] = eb1 + (size_t)nb * 1024;
        ga.C[nb] = e1p + (size_t)nb * 4194304;
    }
    tc_gemm<0,0,0,true,true><<<dim3(8,16,4), 256, DYNSM>>>(ga, 2048, 1024, 2048,
                                                           4194304, 8388608, 2097152);
    // enc2
    for (int nb = 0; nb < 4; nb++) {
        ga.A[nb] = e1p + (size_t)nb * 4194304;
        ga.B[nb] = ew2p + (size_t)nb * 524288;
        ga.bias[nb] = eb2 + (size_t)nb * 512;
        ga.C[nb] = e2p + (size_t)nb * 2097152;
    }
    tc_gemm<0,0,0,true,false><<<dim3(4,16,4), 256, DYNSM>>>(ga, 2048, 512, 1024,
                                                            2097152, 2097152, 1048576);
    // XP = E2 @ wxh^T
    for (int nb = 0; nb < 4; nb++) {
        ga.A[nb] = e2p + (size_t)nb * 2097152;
        ga.B[nb] = wxhp + (size_t)nb * 262144;
        ga.C[nb] = xpp + (size_t)nb * 2097152;
    }
    tc_gemm<0,0,0,false,false><<<dim3(4,16,4), 256, DYNSM>>>(ga, 2048, 512, 512,
                                                             1048576, 1048576, 1048576);
    // RNN fold -> PR fp32
    for (int nb = 0; nb < 4; nb++) {
        ga.A[nb] = xpp + (size_t)nb * 2097152;
        ga.B[nb] = rp + (size_t)nb * 12 * 524288;
        ga.C[nb] = prf + (size_t)nb * 524288;
    }
    tc_gemm<0,1,3,false,false><<<dim3(16,2,4), 256, DYNSM>>>(ga, 256, 2048, 4096,
                                                             1048576, 262144, 0);
    // LN -> PR pairs
    ln_kernel<<<512, 256>>>(prf, lng, lnb, prp);

    // dec1
    for (int nb = 0; nb < 4; nb++) {
        ga.A[nb] = prp + (size_t)nb * 1048576;
        ga.B[nb] = dw1p + (size_t)nb * 524288;
        ga.bias[nb] = db1 + (size_t)nb * 1024;
        ga.C[nb] = dhp + (size_t)nb * 2097152;
    }
    tc_gemm<0,0,0,true,true><<<dim3(8,8,4), 256, DYNSM>>>(ga, 1024, 1024, 512,
                                                          524288, 2097152, 1048576);
    // dec2 fused final
    ga.A[0] = dhp;
    ga.B[0] = dw2p;
    ga.bias[0] = db2;
    ga.C[0] = out;
    tc_gemm<1,3,2,false,false><<<dim3(16,8,1), 256, DYNSM>>>(ga, 1024, 2048, 4096,
                                                             1048576, 8388608, 0);
}